// round 11
// baseline (speedup 1.0000x reference)
#include <cuda_runtime.h>
#include <cuda_fp16.h>
#include <cstdint>
#include <cstddef>

// Problem constants
#define BB 4096
#define DD 4096
#define HH 2048
#define TT 8
#define MM 6

#define GAP_THR 5e-4f

// Scratch (device globals)
__device__ float g_h[(size_t)BB * HH];
__device__ float g_enc[(size_t)BB * HH];
__device__ float g_xs[(size_t)BB * DD];
__device__ int   g_idx[BB * TT];
__device__ int   g_fb_count;
__device__ int   g_fb_list[BB];

// ---------------------------------------------------------------------------
// helpers
// ---------------------------------------------------------------------------
__device__ __forceinline__ uint32_t smem_u32(const void* p) {
    uint32_t a;
    asm("{ .reg .u64 t; cvta.to.shared.u64 t, %1; cvt.u32.u64 %0, t; }" : "=r"(a) : "l"(p));
    return a;
}
__device__ __forceinline__ uint32_t lds_u32(uint32_t a) {
    uint32_t v; asm volatile("ld.shared.u32 %0, [%1];" : "=r"(v) : "r"(a)); return v;
}
__device__ __forceinline__ void sts_v4(uint32_t a, uint32_t x, uint32_t y, uint32_t z, uint32_t w) {
    asm volatile("st.shared.v4.u32 [%0], {%1,%2,%3,%4};" :: "r"(a), "r"(x), "r"(y), "r"(z), "r"(w) : "memory");
}

// fp16 split of two adjacent fp32 values -> (hi half2, lo half2)
__device__ __forceinline__ void h2_split(float f0, float f1, uint32_t& hi, uint32_t& lo) {
    half2 h = __floats2half2_rn(f0, f1);
    float2 hf = __half22float2(h);
    half2 l = __floats2half2_rn(f0 - hf.x, f1 - hf.y);
    hi = *(uint32_t*)&h;
    lo = *(uint32_t*)&l;
}

__device__ __forceinline__ void mma_f16(float* d, const uint32_t* a, uint32_t b0, uint32_t b1) {
    asm volatile(
        "mma.sync.aligned.m16n8k16.row.col.f32.f16.f16.f32 "
        "{%0,%1,%2,%3}, {%4,%5,%6,%7}, {%8,%9}, {%0,%1,%2,%3};"
        : "+f"(d[0]), "+f"(d[1]), "+f"(d[2]), "+f"(d[3])
        : "r"(a[0]), "r"(a[1]), "r"(a[2]), "r"(a[3]), "r"(b0), "r"(b1));
}

// ---------------------------------------------------------------------------
// GEMM: C[4096, 2048] = op(A[4096,K] @ W[K,2048] + bias)
// fp16 3-term split (hi*hi + lo*hi + hi*lo) on mma.sync.m16n8k16.
// Producer-side split; double-buffered smem; ONE __syncthreads per chunk;
// term-major MMA ordering (acc reuse distance = 16 MMAs); all 8 B fragments
// resident per ks so LDS latency hides under the MMA stream.
// smem per stage (u32 words): A 128x36 (cols 0-15 hi-pairs, 16-31 lo-pairs),
//                             B 16x264 (cols 0-127 hi, 132-259 lo)
// ---------------------------------------------------------------------------
#define A_WORDS (128 * 36)     // 4608
#define B_WORDS (16 * 264)     // 4224
#define STAGE_WORDS (A_WORDS + B_WORDS)   // 8832 -> 35328 B
#define GEMM_SMEM (2 * STAGE_WORDS * 4)   // 70656 B

__global__ __launch_bounds__(256, 1)
void hmma_gemm(const float* __restrict__ A, const float* __restrict__ W,
               const float* __restrict__ bias, float* __restrict__ C,
               int K, int relu)
{
    extern __shared__ uint32_t sm[];
    const uint32_t sbase = smem_u32(sm);

    const int t   = threadIdx.x;
    const int wid = t >> 5;
    const int lid = t & 31;
    const int g   = lid >> 2;
    const int t4  = lid & 3;
    const int wm  = wid & 3;      // 4 x 32 rows
    const int wn  = wid >> 2;     // 2 x 64 cols

    const int m0 = blockIdx.y * 128;
    const int n0 = blockIdx.x * 128;

    // producer mappings
    const int aRow = t >> 1;              // 0..127
    const int aP8  = (t & 1) * 8;         // pair offset 0 or 8
    const float* Ag = A + (size_t)(m0 + aRow) * K + aP8 * 2;
    const int bP = t >> 4;                // 0..15 (k-pair)
    const int bN = (t & 15) * 8;          // 0..120
    const float* Bg = W + (size_t)(2 * bP) * HH + n0 + bN;

    const uint32_t aSts = sbase + (uint32_t)(aRow * 36 + aP8) * 4u;
    const uint32_t bSts = sbase + (uint32_t)(A_WORDS + bP * 264 + bN) * 4u;

    float acc[2][8][4];
#pragma unroll
    for (int i = 0; i < 2; i++)
#pragma unroll
        for (int j = 0; j < 8; j++)
#pragma unroll
            for (int q = 0; q < 4; q++) acc[i][j][q] = 0.0f;

    const int NC = K / 32;

    float4 ra[4], rb0[2], rb1[2];

    // producer: convert current regs and STS into stage buffer
    auto convert_sts = [&](uint32_t soff) {
        const float* af = (const float*)ra;
        uint32_t hi[8], lo[8];
#pragma unroll
        for (int j = 0; j < 8; j++)
            h2_split(af[2 * j], af[2 * j + 1], hi[j], lo[j]);
        sts_v4(aSts + soff,      hi[0], hi[1], hi[2], hi[3]);
        sts_v4(aSts + soff + 16, hi[4], hi[5], hi[6], hi[7]);
        sts_v4(aSts + soff + 64, lo[0], lo[1], lo[2], lo[3]);
        sts_v4(aSts + soff + 80, lo[4], lo[5], lo[6], lo[7]);
        const float* b0f = (const float*)rb0;
        const float* b1f = (const float*)rb1;
#pragma unroll
        for (int j = 0; j < 8; j++)
            h2_split(b0f[j], b1f[j], hi[j], lo[j]);
        sts_v4(bSts + soff,       hi[0], hi[1], hi[2], hi[3]);
        sts_v4(bSts + soff + 16,  hi[4], hi[5], hi[6], hi[7]);
        sts_v4(bSts + soff + 528, lo[0], lo[1], lo[2], lo[3]);
        sts_v4(bSts + soff + 544, lo[4], lo[5], lo[6], lo[7]);
    };
    auto ldg_chunk = [&](int c) {
        const float* ap = Ag + (size_t)c * 32;
#pragma unroll
        for (int q = 0; q < 4; q++) ra[q] = *(const float4*)(ap + 4 * q);
        const float* bp = Bg + (size_t)c * 32 * HH;
#pragma unroll
        for (int q = 0; q < 2; q++) {
            rb0[q] = *(const float4*)(bp + 4 * q);
            rb1[q] = *(const float4*)(bp + HH + 4 * q);
        }
    };

    // consumer: one ks (16-k) block: load fragments, term-major MMAs
    auto compute_ks = [&](uint32_t sA, uint32_t sB, int ks) {
        uint32_t Ahi[2][4], Alo[2][4];
#pragma unroll
        for (int mt = 0; mt < 2; mt++) {
            const uint32_t r0 = (uint32_t)(wm * 32 + mt * 16 + g) * 36u;
            const uint32_t r8 = r0 + 8u * 36u;
            const uint32_t p  = (uint32_t)(8 * ks + t4);
            Ahi[mt][0] = lds_u32(sA + (r0 + p) * 4u);
            Ahi[mt][1] = lds_u32(sA + (r8 + p) * 4u);
            Ahi[mt][2] = lds_u32(sA + (r0 + p + 4u) * 4u);
            Ahi[mt][3] = lds_u32(sA + (r8 + p + 4u) * 4u);
            Alo[mt][0] = lds_u32(sA + (r0 + p + 16u) * 4u);
            Alo[mt][1] = lds_u32(sA + (r8 + p + 16u) * 4u);
            Alo[mt][2] = lds_u32(sA + (r0 + p + 20u) * 4u);
            Alo[mt][3] = lds_u32(sA + (r8 + p + 20u) * 4u);
        }
        uint32_t Bh0[8], Bh1[8], Bl0[8], Bl1[8];
        const uint32_t pr0 = (uint32_t)(8 * ks + t4) * 264u;
        const uint32_t pr1 = pr0 + 4u * 264u;
#pragma unroll
        for (int nt = 0; nt < 8; nt++) {
            const uint32_t n = (uint32_t)(wn * 64 + nt * 8 + g);
            Bh0[nt] = lds_u32(sB + (pr0 + n) * 4u);
            Bh1[nt] = lds_u32(sB + (pr1 + n) * 4u);
            Bl0[nt] = lds_u32(sB + (pr0 + 132u + n) * 4u);
            Bl1[nt] = lds_u32(sB + (pr1 + 132u + n) * 4u);
        }
        // term-major: acc reuse distance = 16 MMAs
#pragma unroll
        for (int nt = 0; nt < 8; nt++)
#pragma unroll
            for (int mt = 0; mt < 2; mt++)
                mma_f16(acc[mt][nt], Ahi[mt], Bh0[nt], Bh1[nt]);
#pragma unroll
        for (int nt = 0; nt < 8; nt++)
#pragma unroll
            for (int mt = 0; mt < 2; mt++)
                mma_f16(acc[mt][nt], Alo[mt], Bh0[nt], Bh1[nt]);
#pragma unroll
        for (int nt = 0; nt < 8; nt++)
#pragma unroll
            for (int mt = 0; mt < 2; mt++)
                mma_f16(acc[mt][nt], Ahi[mt], Bl0[nt], Bl1[nt]);
    };

    // pipeline prologue: chunk 0 -> buf0 ; prefetch chunk 1
    ldg_chunk(0);
    convert_sts(0);
    ldg_chunk(1);
    __syncthreads();

    for (int c = 0; c < NC; c++) {
        const uint32_t soff  = (uint32_t)((c & 1) * STAGE_WORDS) * 4u;
        const uint32_t nsoff = (uint32_t)(((c + 1) & 1) * STAGE_WORDS) * 4u;
        const uint32_t sA = sbase + soff;
        const uint32_t sB = sbase + soff + A_WORDS * 4u;

        compute_ks(sA, sB, 0);
        if (c + 1 < NC) convert_sts(nsoff);   // STS drains under ks=1 MMAs
        compute_ks(sA, sB, 1);
        if (c + 2 < NC) ldg_chunk(c + 2);
        __syncthreads();
    }

    // epilogue: c0,c1 at (row, 2t4..2t4+1), c2,c3 at (row+8, same cols)
#pragma unroll
    for (int mt = 0; mt < 2; mt++) {
        int row = m0 + wm * 32 + mt * 16 + g;
#pragma unroll
        for (int nt = 0; nt < 8; nt++) {
            int col = n0 + wn * 64 + nt * 8 + 2 * t4;
            float2 bv = *(const float2*)(bias + col);
            float v0 = acc[mt][nt][0] + bv.x;
            float v1 = acc[mt][nt][1] + bv.y;
            float v2 = acc[mt][nt][2] + bv.x;
            float v3 = acc[mt][nt][3] + bv.y;
            if (relu) {
                v0 = fmaxf(v0, 0.f); v1 = fmaxf(v1, 0.f);
                v2 = fmaxf(v2, 0.f); v3 = fmaxf(v3, 0.f);
            }
            *(float2*)(C + (size_t)row * HH + col) = make_float2(v0, v1);
            *(float2*)(C + (size_t)(row + 8) * HH + col) = make_float2(v2, v3);
        }
    }
}

// ---------------------------------------------------------------------------
__global__ void reset_kernel() { g_fb_count = 0; }

// ---------------------------------------------------------------------------
// logits = g_enc @ Ws + bs ; argmax -> g_idx ; near-ties flagged for fallback
// ---------------------------------------------------------------------------
__global__ __launch_bounds__(256, 4)
void logits_argmax_kernel(const float* __restrict__ Ws, const float* __restrict__ bs,
                          float* __restrict__ out_logits, int write_logits)
{
    __shared__ float es[16][128];
    __shared__ float ws[128][48];
    __shared__ float ls[16][48];
    __shared__ int   sflag[16];

    int b0 = blockIdx.x * 16;
    int t  = threadIdx.x;
    int r  = t >> 4;
    int c  = t & 15;

    if (t < 16) sflag[t] = 0;

    float acc0 = 0.f, acc1 = 0.f, acc2 = 0.f;

    for (int k0 = 0; k0 < HH; k0 += 128) {
        for (int i = t; i < 512; i += 256) {
            int rr = i >> 5, cc = (i & 31) << 2;
            *(float4*)&es[rr][cc] =
                *(const float4*)(g_enc + (size_t)(b0 + rr) * HH + k0 + cc);
        }
        for (int i = t; i < 1536; i += 256) {
            int rr = i / 12, cc = (i % 12) << 2;
            *(float4*)&ws[rr][cc] = *(const float4*)(Ws + (size_t)(k0 + rr) * 48 + cc);
        }
        __syncthreads();
        float p0 = 0.f, p1 = 0.f, p2 = 0.f;
#pragma unroll 4
        for (int k = 0; k < 128; k++) {
            float e = es[r][k];
            p0 = fmaf(e, ws[k][c],      p0);
            p1 = fmaf(e, ws[k][c + 16], p1);
            p2 = fmaf(e, ws[k][c + 32], p2);
        }
        acc0 += p0; acc1 += p1; acc2 += p2;
        __syncthreads();
    }

    ls[r][c]      = acc0 + bs[c];
    ls[r][c + 16] = acc1 + bs[c + 16];
    ls[r][c + 32] = acc2 + bs[c + 32];
    __syncthreads();

    if (write_logits) {
        for (int i = t; i < 16 * 48; i += 256) {
            int rr = i / 48, cc = i % 48;
            out_logits[(size_t)(b0 + rr) * 48 + cc] = ls[rr][cc];
        }
    }
    if (t < 128) {
        int rr = t >> 3, tt = t & 7;
        const float* lp = &ls[rr][tt * 6];
        float best = lp[0], second = -3.4e38f;
        int bi = 0;
#pragma unroll
        for (int m = 1; m < 6; m++) {
            float v = lp[m];
            if (v > best) { second = best; best = v; bi = m; }
            else if (v > second) second = v;
        }
        g_idx[(b0 + rr) * TT + tt] = bi;
        if (best - second < GAP_THR) sflag[rr] = 1;
    }
    __syncthreads();
    if (t < 16 && sflag[t]) {
        int pos = atomicAdd(&g_fb_count, 1);
        g_fb_list[pos] = b0 + t;
    }
}

// ---------------------------------------------------------------------------
// Exact fp32 fallback: recompute h -> enc -> logits -> argmax for flagged b.
// ---------------------------------------------------------------------------
__global__ __launch_bounds__(256, 1)
void fallback_kernel(const float* __restrict__ x,
                     const float* __restrict__ W1, const float* __restrict__ b1,
                     const float* __restrict__ W2, const float* __restrict__ b2,
                     const float* __restrict__ Ws, const float* __restrict__ bs)
{
    __shared__ float xs[1024];
    __shared__ float hs[2048];
    __shared__ float es2[2048];
    __shared__ float ls[48];

    const int t = threadIdx.x;
    const int total = g_fb_count;

    for (int idx = blockIdx.x; idx < total; idx += gridDim.x) {
        const int b = g_fb_list[idx];

        float ha[8];
#pragma unroll
        for (int m = 0; m < 8; m++) ha[m] = 0.f;
        for (int k0 = 0; k0 < DD; k0 += 1024) {
            __syncthreads();
            for (int i = t; i < 256; i += 256)
                *(float4*)&xs[i * 4] = *(const float4*)(x + (size_t)b * DD + k0 + i * 4);
            __syncthreads();
            for (int k = 0; k < 1024; k++) {
                float xv = xs[k];
                const float* wrow = W1 + (size_t)(k0 + k) * HH + t;
#pragma unroll
                for (int m = 0; m < 8; m++)
                    ha[m] = fmaf(xv, wrow[256 * m], ha[m]);
            }
        }
        __syncthreads();
#pragma unroll
        for (int m = 0; m < 8; m++)
            hs[t + 256 * m] = fmaxf(ha[m] + b1[t + 256 * m], 0.f);
        __syncthreads();

        float ea[8];
#pragma unroll
        for (int m = 0; m < 8; m++) ea[m] = 0.f;
        for (int k = 0; k < HH; k++) {
            float hv = hs[k];
            const float* wrow = W2 + (size_t)k * HH + t;
#pragma unroll
            for (int m = 0; m < 8; m++)
                ea[m] = fmaf(hv, wrow[256 * m], ea[m]);
        }
#pragma unroll
        for (int m = 0; m < 8; m++)
            es2[t + 256 * m] = ea[m] + b2[t + 256 * m];
        __syncthreads();

        if (t < 48) {
            float a = 0.f;
            for (int k = 0; k < HH; k++)
                a = fmaf(es2[k], Ws[(size_t)k * 48 + t], a);
            ls[t] = a + bs[t];
        }
        __syncthreads();
        if (t < 8) {
            const float* lp = &ls[t * 6];
            float best = lp[0]; int bi = 0;
#pragma unroll
            for (int m = 1; m < 6; m++) {
                float v = lp[m];
                if (v > best) { best = v; bi = m; }
            }
            g_idx[b * TT + t] = bi;
        }
        __syncthreads();
    }
}

// ---------------------------------------------------------------------------
// Bitonic sort of rows [b_off, b_off+grid) of x -> g_xs
// ---------------------------------------------------------------------------
__global__ __launch_bounds__(1024, 2)
void sort_rows_kernel(const float* __restrict__ x, int b_off)
{
    __shared__ float s[4096];
    int b = blockIdx.x + b_off;
    const float* xp = x + (size_t)b * DD;
    for (int i = threadIdx.x; i < 4096; i += 1024) s[i] = xp[i];
    __syncthreads();

    for (int k = 2; k <= 4096; k <<= 1) {
        for (int j = k >> 1; j > 0; j >>= 1) {
#pragma unroll
            for (int base = 0; base < 4096; base += 1024) {
                int i   = base + threadIdx.x;
                int ixj = i ^ j;
                if (ixj > i) {
                    bool asc = ((i & k) == 0);
                    float a = s[i], bb = s[ixj];
                    if ((a > bb) == asc) { s[i] = bb; s[ixj] = a; }
                }
            }
            __syncthreads();
        }
    }
    float* op = g_xs + (size_t)b * DD;
    for (int i = threadIdx.x; i < 4096; i += 1024) op[i] = s[i];
}

// ---------------------------------------------------------------------------
// Collapsed scan + emit: outputs[b,t,:] = a_t * perm_t(x_b) + c_t
// ---------------------------------------------------------------------------
__global__ __launch_bounds__(256, 4)
void emit_kernel(const float* __restrict__ x,
                 const float* __restrict__ add_s, const float* __restrict__ sub_s,
                 const float* __restrict__ mul_s, const float* __restrict__ div_s,
                 float* __restrict__ out)
{
    __shared__ float sa[8], sb[8];
    __shared__ int   sm8[8];
    int b = blockIdx.x;

    if (threadIdx.x == 0) {
        float A = 1.0f, Bc = 0.0f;
        int mode = 0;
        float ad = *add_s, su = *sub_s, mu = *mul_s;
        float dv = *div_s + 1e-5f;
#pragma unroll
        for (int t = 0; t < 8; t++) {
            int m = g_idx[b * 8 + t];
            switch (m) {
                case 0: mode = 2;              break;
                case 1: mode ^= 1;             break;
                case 2: Bc += ad;              break;
                case 3: Bc -= su;              break;
                case 4: A *= mu; Bc *= mu;     break;
                case 5: A /= dv; Bc /= dv;     break;
            }
            sa[t] = A; sb[t] = Bc; sm8[t] = mode;
        }
    }
    __syncthreads();

    const float4* xr  = (const float4*)(x    + (size_t)b * DD);
    const float4* xsr = (const float4*)(g_xs + (size_t)b * DD);
    float* ob = out + (size_t)b * ((size_t)TT * DD);
    const int Q = DD / 4;

#pragma unroll 1
    for (int t = 0; t < 8; t++) {
        float A = sa[t], Bc = sb[t];
        int mode = sm8[t];
        const float4* src = (mode & 2) ? xsr : xr;
        bool rev = (mode & 1);
        float4* op = (float4*)(ob + (size_t)t * DD);
        for (int i = threadIdx.x; i < Q; i += 256) {
            float4 v;
            if (!rev) {
                v = src[i];
            } else {
                float4 u = src[Q - 1 - i];
                v.x = u.w; v.y = u.z; v.z = u.y; v.w = u.x;
            }
            v.x = fmaf(A, v.x, Bc);
            v.y = fmaf(A, v.y, Bc);
            v.z = fmaf(A, v.z, Bc);
            v.w = fmaf(A, v.w, Bc);
            op[i] = v;
        }
    }
}

// ---------------------------------------------------------------------------
extern "C" void kernel_launch(void* const* d_in, const int* in_sizes, int n_in,
                              void* d_out, int out_size)
{
    const float* x     = (const float*)d_in[0];
    const float* W1    = (const float*)d_in[1];
    const float* b1    = (const float*)d_in[2];
    const float* W2    = (const float*)d_in[3];
    const float* b2    = (const float*)d_in[4];
    const float* Ws    = (const float*)d_in[5];
    const float* bs    = (const float*)d_in[6];
    const float* add_s = (const float*)d_in[7];
    const float* sub_s = (const float*)d_in[8];
    const float* mul_s = (const float*)d_in[9];
    const float* div_s = (const float*)d_in[10];
    float* out = (float*)d_out;

    const size_t out_main = (size_t)BB * TT * DD;
    const size_t out_need = out_main + (size_t)BB * TT * MM;
    int write_logits = ((size_t)out_size >= out_need) ? 1 : 0;
    float* out_logits = out + out_main;

    cudaFuncSetAttribute(hmma_gemm, cudaFuncAttributeMaxDynamicSharedMemorySize, GEMM_SMEM);

    float* d_gh;  cudaGetSymbolAddress((void**)&d_gh,  g_h);
    float* d_enc; cudaGetSymbolAddress((void**)&d_enc, g_enc);

    // launch order: gemms at indices 3,4 (ncu -s window)
    sort_rows_kernel<<<BB / 2, 1024>>>(x, 0);
    sort_rows_kernel<<<BB / 2, 1024>>>(x, BB / 2);
    reset_kernel<<<1, 1>>>();

    dim3 g(HH / 128, BB / 128);  // (16, 32)
    hmma_gemm<<<g, 256, GEMM_SMEM>>>(x,    W1, b1, d_gh,  DD, 1);  // g_h = relu(x@W1+b1)
    hmma_gemm<<<g, 256, GEMM_SMEM>>>(d_gh, W2, b2, d_enc, HH, 0);  // g_enc = g_h@W2+b2

    logits_argmax_kernel<<<BB / 16, 256>>>(Ws, bs, out_logits, write_logits);

    fallback_kernel<<<64, 256>>>(x, W1, b1, W2, b2, Ws, bs);

    emit_kernel<<<BB, 256>>>(x, add_s, sub_s, mul_s, div_s, out);
}

// round 12
// speedup vs baseline: 1.1784x; 1.1784x over previous
#include <cuda_runtime.h>
#include <cuda_fp16.h>
#include <cstdint>
#include <cstddef>

// Problem constants
#define BB 4096
#define DD 4096
#define HH 2048
#define TT 8
#define MM 6

#define GAP_THR 5e-4f

// Scratch (device globals)
__device__ float g_h[(size_t)BB * HH];
__device__ float g_xs[(size_t)BB * DD];
__device__ float g_wc[(size_t)HH * 48];   // W2 @ Ws (folded controller tail)
__device__ float g_bc[48];                // b2 @ Ws + bs
__device__ int   g_idx[BB * TT];
__device__ int   g_fb_count;
__device__ int   g_fb_list[BB];

// ---------------------------------------------------------------------------
// helpers
// ---------------------------------------------------------------------------
__device__ __forceinline__ uint32_t smem_u32(const void* p) {
    uint32_t a;
    asm("{ .reg .u64 t; cvta.to.shared.u64 t, %1; cvt.u32.u64 %0, t; }" : "=r"(a) : "l"(p));
    return a;
}
__device__ __forceinline__ uint32_t lds_u32(uint32_t a) {
    uint32_t v; asm volatile("ld.shared.u32 %0, [%1];" : "=r"(v) : "r"(a)); return v;
}
__device__ __forceinline__ void sts_v4(uint32_t a, uint32_t x, uint32_t y, uint32_t z, uint32_t w) {
    asm volatile("st.shared.v4.u32 [%0], {%1,%2,%3,%4};" :: "r"(a), "r"(x), "r"(y), "r"(z), "r"(w) : "memory");
}

// fp16 split of two adjacent fp32 values -> (hi half2, lo half2)
__device__ __forceinline__ void h2_split(float f0, float f1, uint32_t& hi, uint32_t& lo) {
    half2 h = __floats2half2_rn(f0, f1);
    float2 hf = __half22float2(h);
    half2 l = __floats2half2_rn(f0 - hf.x, f1 - hf.y);
    hi = *(uint32_t*)&h;
    lo = *(uint32_t*)&l;
}

__device__ __forceinline__ void mma_f16(float* d, const uint32_t* a, uint32_t b0, uint32_t b1) {
    asm volatile(
        "mma.sync.aligned.m16n8k16.row.col.f32.f16.f16.f32 "
        "{%0,%1,%2,%3}, {%4,%5,%6,%7}, {%8,%9}, {%0,%1,%2,%3};"
        : "+f"(d[0]), "+f"(d[1]), "+f"(d[2]), "+f"(d[3])
        : "r"(a[0]), "r"(a[1]), "r"(a[2]), "r"(a[3]), "r"(b0), "r"(b1));
}

// ---------------------------------------------------------------------------
// GEMM (R10 config — best measured): h = relu(x @ W1 + b1)
// fp16 3-term split on mma.sync.m16n8k16, producer-side split,
// double-buffered smem, launch_bounds(256,2).
// ---------------------------------------------------------------------------
#define A_WORDS (128 * 36)     // 4608
#define B_WORDS (16 * 264)     // 4224
#define STAGE_WORDS (A_WORDS + B_WORDS)   // 8832 -> 35328 B
#define GEMM_SMEM (2 * STAGE_WORDS * 4)   // 70656 B

__global__ __launch_bounds__(256, 2)
void hmma_gemm(const float* __restrict__ A, const float* __restrict__ W,
               const float* __restrict__ bias, float* __restrict__ C,
               int K, int relu)
{
    extern __shared__ uint32_t sm[];
    const uint32_t sbase = smem_u32(sm);

    const int t   = threadIdx.x;
    const int wid = t >> 5;
    const int lid = t & 31;
    const int g   = lid >> 2;
    const int t4  = lid & 3;
    const int wm  = wid & 3;      // 4 x 32 rows
    const int wn  = wid >> 2;     // 2 x 64 cols

    const int m0 = blockIdx.y * 128;
    const int n0 = blockIdx.x * 128;

    // producer mappings
    const int aRow = t >> 1;
    const int aP8  = (t & 1) * 8;
    const float* Ag = A + (size_t)(m0 + aRow) * K + aP8 * 2;
    const int bP = t >> 4;
    const int bN = (t & 15) * 8;
    const float* Bg = W + (size_t)(2 * bP) * HH + n0 + bN;

    const uint32_t aSts = sbase + (uint32_t)(aRow * 36 + aP8) * 4u;
    const uint32_t bSts = sbase + (uint32_t)(A_WORDS + bP * 264 + bN) * 4u;

    float acc[2][8][4];
#pragma unroll
    for (int i = 0; i < 2; i++)
#pragma unroll
        for (int j = 0; j < 8; j++)
#pragma unroll
            for (int q = 0; q < 4; q++) acc[i][j][q] = 0.0f;

    const int NC = K / 32;

    // prefetch chunk 0
    float4 ra[4], rb0[2], rb1[2];
#pragma unroll
    for (int q = 0; q < 4; q++) ra[q] = *(const float4*)(Ag + 4 * q);
#pragma unroll
    for (int q = 0; q < 2; q++) {
        rb0[q] = *(const float4*)(Bg + 4 * q);
        rb1[q] = *(const float4*)(Bg + HH + 4 * q);
    }

    for (int c = 0; c < NC; c++) {
        const uint32_t soff = (uint32_t)((c & 1) * STAGE_WORDS) * 4u;

        // ---- convert + STS current chunk ----
        {
            const float* af = (const float*)ra;
            uint32_t hi[8], lo[8];
#pragma unroll
            for (int j = 0; j < 8; j++)
                h2_split(af[2 * j], af[2 * j + 1], hi[j], lo[j]);
            sts_v4(aSts + soff,      hi[0], hi[1], hi[2], hi[3]);
            sts_v4(aSts + soff + 16, hi[4], hi[5], hi[6], hi[7]);
            sts_v4(aSts + soff + 64, lo[0], lo[1], lo[2], lo[3]);
            sts_v4(aSts + soff + 80, lo[4], lo[5], lo[6], lo[7]);

            const float* b0f = (const float*)rb0;
            const float* b1f = (const float*)rb1;
#pragma unroll
            for (int j = 0; j < 8; j++)
                h2_split(b0f[j], b1f[j], hi[j], lo[j]);
            sts_v4(bSts + soff,       hi[0], hi[1], hi[2], hi[3]);
            sts_v4(bSts + soff + 16,  hi[4], hi[5], hi[6], hi[7]);
            sts_v4(bSts + soff + 528, lo[0], lo[1], lo[2], lo[3]);
            sts_v4(bSts + soff + 544, lo[4], lo[5], lo[6], lo[7]);
        }
        __syncthreads();

        // ---- prefetch next chunk ----
        if (c + 1 < NC) {
            const float* ap = Ag + (size_t)(c + 1) * 32;
#pragma unroll
            for (int q = 0; q < 4; q++) ra[q] = *(const float4*)(ap + 4 * q);
            const float* bp = Bg + (size_t)(c + 1) * 32 * HH;
#pragma unroll
            for (int q = 0; q < 2; q++) {
                rb0[q] = *(const float4*)(bp + 4 * q);
                rb1[q] = *(const float4*)(bp + HH + 4 * q);
            }
        }

        // ---- compute on current stage (pure LDS + MMA) ----
        const uint32_t sA = sbase + soff;
        const uint32_t sB = sbase + soff + A_WORDS * 4u;

#pragma unroll
        for (int ks = 0; ks < 2; ks++) {
            uint32_t Ahi[2][4], Alo[2][4];
#pragma unroll
            for (int mt = 0; mt < 2; mt++) {
                const uint32_t r0 = (uint32_t)(wm * 32 + mt * 16 + g) * 36u;
                const uint32_t r8 = r0 + 8u * 36u;
                const uint32_t p  = (uint32_t)(8 * ks + t4);
                Ahi[mt][0] = lds_u32(sA + (r0 + p) * 4u);
                Ahi[mt][1] = lds_u32(sA + (r8 + p) * 4u);
                Ahi[mt][2] = lds_u32(sA + (r0 + p + 4u) * 4u);
                Ahi[mt][3] = lds_u32(sA + (r8 + p + 4u) * 4u);
                Alo[mt][0] = lds_u32(sA + (r0 + p + 16u) * 4u);
                Alo[mt][1] = lds_u32(sA + (r8 + p + 16u) * 4u);
                Alo[mt][2] = lds_u32(sA + (r0 + p + 20u) * 4u);
                Alo[mt][3] = lds_u32(sA + (r8 + p + 20u) * 4u);
            }
            const uint32_t pr0 = (uint32_t)(8 * ks + t4) * 264u;
            const uint32_t pr1 = pr0 + 4u * 264u;
#pragma unroll
            for (int nt = 0; nt < 8; nt++) {
                const uint32_t n = (uint32_t)(wn * 64 + nt * 8 + g);
                uint32_t bh0 = lds_u32(sB + (pr0 + n) * 4u);
                uint32_t bh1 = lds_u32(sB + (pr1 + n) * 4u);
                uint32_t bl0 = lds_u32(sB + (pr0 + 132u + n) * 4u);
                uint32_t bl1 = lds_u32(sB + (pr1 + 132u + n) * 4u);
#pragma unroll
                for (int mt = 0; mt < 2; mt++) {
                    mma_f16(acc[mt][nt], Ahi[mt], bh0, bh1);
                    mma_f16(acc[mt][nt], Alo[mt], bh0, bh1);
                    mma_f16(acc[mt][nt], Ahi[mt], bl0, bl1);
                }
            }
        }
        __syncthreads();
    }

    // epilogue
#pragma unroll
    for (int mt = 0; mt < 2; mt++) {
        int row = m0 + wm * 32 + mt * 16 + g;
#pragma unroll
        for (int nt = 0; nt < 8; nt++) {
            int col = n0 + wn * 64 + nt * 8 + 2 * t4;
            float2 bv = *(const float2*)(bias + col);
            float v0 = acc[mt][nt][0] + bv.x;
            float v1 = acc[mt][nt][1] + bv.y;
            float v2 = acc[mt][nt][2] + bv.x;
            float v3 = acc[mt][nt][3] + bv.y;
            if (relu) {
                v0 = fmaxf(v0, 0.f); v1 = fmaxf(v1, 0.f);
                v2 = fmaxf(v2, 0.f); v3 = fmaxf(v3, 0.f);
            }
            *(float2*)(C + (size_t)row * HH + col) = make_float2(v0, v1);
            *(float2*)(C + (size_t)(row + 8) * HH + col) = make_float2(v2, v3);
        }
    }
}

// ---------------------------------------------------------------------------
__global__ void reset_kernel() { g_fb_count = 0; }

// ---------------------------------------------------------------------------
// Wc = W2 @ Ws  [2048 x 48], exact fp32 with chunked accumulation
// ---------------------------------------------------------------------------
__global__ __launch_bounds__(256, 4)
void wc_kernel(const float* __restrict__ W2, const float* __restrict__ Ws)
{
    __shared__ float es[16][128];
    __shared__ float ws[128][48];

    int r0 = blockIdx.x * 16;   // 128 blocks cover 2048 rows
    int t  = threadIdx.x;
    int r  = t >> 4;
    int c  = t & 15;

    float a0 = 0.f, a1 = 0.f, a2 = 0.f;

    for (int k0 = 0; k0 < HH; k0 += 128) {
        for (int i = t; i < 512; i += 256) {
            int rr = i >> 5, cc = (i & 31) << 2;
            *(float4*)&es[rr][cc] =
                *(const float4*)(W2 + (size_t)(r0 + rr) * HH + k0 + cc);
        }
        for (int i = t; i < 1536; i += 256) {
            int rr = i / 12, cc = (i % 12) << 2;
            *(float4*)&ws[rr][cc] = *(const float4*)(Ws + (size_t)(k0 + rr) * 48 + cc);
        }
        __syncthreads();
        float p0 = 0.f, p1 = 0.f, p2 = 0.f;
#pragma unroll 4
        for (int k = 0; k < 128; k++) {
            float e = es[r][k];
            p0 = fmaf(e, ws[k][c],      p0);
            p1 = fmaf(e, ws[k][c + 16], p1);
            p2 = fmaf(e, ws[k][c + 32], p2);
        }
        a0 += p0; a1 += p1; a2 += p2;
        __syncthreads();
    }

    g_wc[(size_t)(r0 + r) * 48 + c]      = a0;
    g_wc[(size_t)(r0 + r) * 48 + c + 16] = a1;
    g_wc[(size_t)(r0 + r) * 48 + c + 32] = a2;
}

// bc = b2 @ Ws + bs
__global__ void bc_kernel(const float* __restrict__ b2, const float* __restrict__ Ws,
                          const float* __restrict__ bs)
{
    int j = threadIdx.x;
    if (j < 48) {
        float a = 0.f;
        for (int k = 0; k < HH; k++)
            a = fmaf(b2[k], Ws[(size_t)k * 48 + j], a);
        g_bc[j] = a + bs[j];
    }
}

// ---------------------------------------------------------------------------
// logits = g_h @ g_wc + g_bc ; argmax -> g_idx ; near-ties flagged
// ---------------------------------------------------------------------------
__global__ __launch_bounds__(256, 4)
void logits_argmax_kernel(float* __restrict__ out_logits, int write_logits)
{
    __shared__ float es[16][128];
    __shared__ float ws[128][48];
    __shared__ float ls[16][48];
    __shared__ int   sflag[16];

    int b0 = blockIdx.x * 16;
    int t  = threadIdx.x;
    int r  = t >> 4;
    int c  = t & 15;

    if (t < 16) sflag[t] = 0;

    float acc0 = 0.f, acc1 = 0.f, acc2 = 0.f;

    for (int k0 = 0; k0 < HH; k0 += 128) {
        for (int i = t; i < 512; i += 256) {
            int rr = i >> 5, cc = (i & 31) << 2;
            *(float4*)&es[rr][cc] =
                *(const float4*)(g_h + (size_t)(b0 + rr) * HH + k0 + cc);
        }
        for (int i = t; i < 1536; i += 256) {
            int rr = i / 12, cc = (i % 12) << 2;
            *(float4*)&ws[rr][cc] = *(const float4*)(g_wc + (size_t)(k0 + rr) * 48 + cc);
        }
        __syncthreads();
        float p0 = 0.f, p1 = 0.f, p2 = 0.f;
#pragma unroll 4
        for (int k = 0; k < 128; k++) {
            float e = es[r][k];
            p0 = fmaf(e, ws[k][c],      p0);
            p1 = fmaf(e, ws[k][c + 16], p1);
            p2 = fmaf(e, ws[k][c + 32], p2);
        }
        acc0 += p0; acc1 += p1; acc2 += p2;
        __syncthreads();
    }

    ls[r][c]      = acc0 + g_bc[c];
    ls[r][c + 16] = acc1 + g_bc[c + 16];
    ls[r][c + 32] = acc2 + g_bc[c + 32];
    __syncthreads();

    if (write_logits) {
        for (int i = t; i < 16 * 48; i += 256) {
            int rr = i / 48, cc = i % 48;
            out_logits[(size_t)(b0 + rr) * 48 + cc] = ls[rr][cc];
        }
    }
    if (t < 128) {
        int rr = t >> 3, tt = t & 7;
        const float* lp = &ls[rr][tt * 6];
        float best = lp[0], second = -3.4e38f;
        int bi = 0;
#pragma unroll
        for (int m = 1; m < 6; m++) {
            float v = lp[m];
            if (v > best) { second = best; best = v; bi = m; }
            else if (v > second) second = v;
        }
        g_idx[(b0 + rr) * TT + tt] = bi;
        if (best - second < GAP_THR) sflag[rr] = 1;
    }
    __syncthreads();
    if (t < 16 && sflag[t]) {
        int pos = atomicAdd(&g_fb_count, 1);
        g_fb_list[pos] = b0 + t;
    }
}

// ---------------------------------------------------------------------------
// Exact fp32 fallback: recompute h -> enc -> logits -> argmax for flagged b.
// ---------------------------------------------------------------------------
__global__ __launch_bounds__(256, 1)
void fallback_kernel(const float* __restrict__ x,
                     const float* __restrict__ W1, const float* __restrict__ b1,
                     const float* __restrict__ W2, const float* __restrict__ b2,
                     const float* __restrict__ Ws, const float* __restrict__ bs)
{
    __shared__ float xs[1024];
    __shared__ float hs[2048];
    __shared__ float es2[2048];
    __shared__ float ls[48];

    const int t = threadIdx.x;
    const int total = g_fb_count;

    for (int idx = blockIdx.x; idx < total; idx += gridDim.x) {
        const int b = g_fb_list[idx];

        float ha[8];
#pragma unroll
        for (int m = 0; m < 8; m++) ha[m] = 0.f;
        for (int k0 = 0; k0 < DD; k0 += 1024) {
            __syncthreads();
            for (int i = t; i < 256; i += 256)
                *(float4*)&xs[i * 4] = *(const float4*)(x + (size_t)b * DD + k0 + i * 4);
            __syncthreads();
            for (int k = 0; k < 1024; k++) {
                float xv = xs[k];
                const float* wrow = W1 + (size_t)(k0 + k) * HH + t;
#pragma unroll
                for (int m = 0; m < 8; m++)
                    ha[m] = fmaf(xv, wrow[256 * m], ha[m]);
            }
        }
        __syncthreads();
#pragma unroll
        for (int m = 0; m < 8; m++)
            hs[t + 256 * m] = fmaxf(ha[m] + b1[t + 256 * m], 0.f);
        __syncthreads();

        float ea[8];
#pragma unroll
        for (int m = 0; m < 8; m++) ea[m] = 0.f;
        for (int k = 0; k < HH; k++) {
            float hv = hs[k];
            const float* wrow = W2 + (size_t)k * HH + t;
#pragma unroll
            for (int m = 0; m < 8; m++)
                ea[m] = fmaf(hv, wrow[256 * m], ea[m]);
        }
#pragma unroll
        for (int m = 0; m < 8; m++)
            es2[t + 256 * m] = ea[m] + b2[t + 256 * m];
        __syncthreads();

        if (t < 48) {
            float a = 0.f;
            for (int k = 0; k < HH; k++)
                a = fmaf(es2[k], Ws[(size_t)k * 48 + t], a);
            ls[t] = a + bs[t];
        }
        __syncthreads();
        if (t < 8) {
            const float* lp = &ls[t * 6];
            float best = lp[0]; int bi = 0;
#pragma unroll
            for (int m = 1; m < 6; m++) {
                float v = lp[m];
                if (v > best) { best = v; bi = m; }
            }
            g_idx[b * TT + t] = bi;
        }
        __syncthreads();
    }
}

// ---------------------------------------------------------------------------
// Bitonic sort of rows [b_off, b_off+grid) of x -> g_xs
// ---------------------------------------------------------------------------
__global__ __launch_bounds__(1024, 2)
void sort_rows_kernel(const float* __restrict__ x, int b_off)
{
    __shared__ float s[4096];
    int b = blockIdx.x + b_off;
    const float* xp = x + (size_t)b * DD;
    for (int i = threadIdx.x; i < 4096; i += 1024) s[i] = xp[i];
    __syncthreads();

    for (int k = 2; k <= 4096; k <<= 1) {
        for (int j = k >> 1; j > 0; j >>= 1) {
#pragma unroll
            for (int base = 0; base < 4096; base += 1024) {
                int i   = base + threadIdx.x;
                int ixj = i ^ j;
                if (ixj > i) {
                    bool asc = ((i & k) == 0);
                    float a = s[i], bb = s[ixj];
                    if ((a > bb) == asc) { s[i] = bb; s[ixj] = a; }
                }
            }
            __syncthreads();
        }
    }
    float* op = g_xs + (size_t)b * DD;
    for (int i = threadIdx.x; i < 4096; i += 1024) op[i] = s[i];
}

// ---------------------------------------------------------------------------
// Collapsed scan + emit: outputs[b,t,:] = a_t * perm_t(x_b) + c_t
// ---------------------------------------------------------------------------
__global__ __launch_bounds__(256, 4)
void emit_kernel(const float* __restrict__ x,
                 const float* __restrict__ add_s, const float* __restrict__ sub_s,
                 const float* __restrict__ mul_s, const float* __restrict__ div_s,
                 float* __restrict__ out)
{
    __shared__ float sa[8], sb[8];
    __shared__ int   sm8[8];
    int b = blockIdx.x;

    if (threadIdx.x == 0) {
        float A = 1.0f, Bc = 0.0f;
        int mode = 0;
        float ad = *add_s, su = *sub_s, mu = *mul_s;
        float dv = *div_s + 1e-5f;
#pragma unroll
        for (int t = 0; t < 8; t++) {
            int m = g_idx[b * 8 + t];
            switch (m) {
                case 0: mode = 2;              break;
                case 1: mode ^= 1;             break;
                case 2: Bc += ad;              break;
                case 3: Bc -= su;              break;
                case 4: A *= mu; Bc *= mu;     break;
                case 5: A /= dv; Bc /= dv;     break;
            }
            sa[t] = A; sb[t] = Bc; sm8[t] = mode;
        }
    }
    __syncthreads();

    const float4* xr  = (const float4*)(x    + (size_t)b * DD);
    const float4* xsr = (const float4*)(g_xs + (size_t)b * DD);
    float* ob = out + (size_t)b * ((size_t)TT * DD);
    const int Q = DD / 4;

#pragma unroll 1
    for (int t = 0; t < 8; t++) {
        float A = sa[t], Bc = sb[t];
        int mode = sm8[t];
        const float4* src = (mode & 2) ? xsr : xr;
        bool rev = (mode & 1);
        float4* op = (float4*)(ob + (size_t)t * DD);
        for (int i = threadIdx.x; i < Q; i += 256) {
            float4 v;
            if (!rev) {
                v = src[i];
            } else {
                float4 u = src[Q - 1 - i];
                v.x = u.w; v.y = u.z; v.z = u.y; v.w = u.x;
            }
            v.x = fmaf(A, v.x, Bc);
            v.y = fmaf(A, v.y, Bc);
            v.z = fmaf(A, v.z, Bc);
            v.w = fmaf(A, v.w, Bc);
            op[i] = v;
        }
    }
}

// ---------------------------------------------------------------------------
extern "C" void kernel_launch(void* const* d_in, const int* in_sizes, int n_in,
                              void* d_out, int out_size)
{
    const float* x     = (const float*)d_in[0];
    const float* W1    = (const float*)d_in[1];
    const float* b1    = (const float*)d_in[2];
    const float* W2    = (const float*)d_in[3];
    const float* b2    = (const float*)d_in[4];
    const float* Ws    = (const float*)d_in[5];
    const float* bs    = (const float*)d_in[6];
    const float* add_s = (const float*)d_in[7];
    const float* sub_s = (const float*)d_in[8];
    const float* mul_s = (const float*)d_in[9];
    const float* div_s = (const float*)d_in[10];
    float* out = (float*)d_out;

    const size_t out_main = (size_t)BB * TT * DD;
    const size_t out_need = out_main + (size_t)BB * TT * MM;
    int write_logits = ((size_t)out_size >= out_need) ? 1 : 0;
    float* out_logits = out + out_main;

    cudaFuncSetAttribute(hmma_gemm, cudaFuncAttributeMaxDynamicSharedMemorySize, GEMM_SMEM);

    float* d_gh;  cudaGetSymbolAddress((void**)&d_gh,  g_h);

    // launch order: gemm1 at index 3 (ncu -s window)
    sort_rows_kernel<<<BB / 2, 1024>>>(x, 0);
    sort_rows_kernel<<<BB / 2, 1024>>>(x, BB / 2);
    reset_kernel<<<1, 1>>>();

    dim3 g(HH / 128, BB / 128);  // (16, 32)
    hmma_gemm<<<g, 256, GEMM_SMEM>>>(x, W1, b1, d_gh, DD, 1);  // g_h = relu(x@W1+b1)

    // folded controller tail: Wc = W2@Ws, bc = b2@Ws + bs  (gemm2 eliminated)
    wc_kernel<<<HH / 16, 256>>>(W2, Ws);
    bc_kernel<<<1, 64>>>(b2, Ws, bs);

    logits_argmax_kernel<<<BB / 16, 256>>>(out_logits, write_logits);

    fallback_kernel<<<64, 256>>>(x, W1, b1, W2, b2, Ws, bs);

    emit_kernel<<<BB, 256>>>(x, add_s, sub_s, mul_s, div_s, out);
}

// round 13
// speedup vs baseline: 1.2414x; 1.0535x over previous
#include <cuda_runtime.h>
#include <cuda_fp16.h>
#include <cstdint>
#include <cstddef>

// Problem constants
#define BB 4096
#define DD 4096
#define HH 2048
#define TT 8
#define MM 6

#define GAP_THR 5e-4f

// Scratch (device globals)
__device__ float g_h[(size_t)BB * HH];
__device__ float g_xs[(size_t)BB * DD];
__device__ float g_wc[(size_t)HH * 48];   // W2 @ Ws
__device__ float g_bc[48];                // b2 @ Ws + bs
__device__ int   g_idx[BB * TT];
__device__ int   g_fb_count;
__device__ int   g_fb_list[BB];

// ---------------------------------------------------------------------------
// helpers
// ---------------------------------------------------------------------------
__device__ __forceinline__ uint32_t smem_u32(const void* p) {
    uint32_t a;
    asm("{ .reg .u64 t; cvta.to.shared.u64 t, %1; cvt.u32.u64 %0, t; }" : "=r"(a) : "l"(p));
    return a;
}
__device__ __forceinline__ uint32_t lds_u32(uint32_t a) {
    uint32_t v; asm volatile("ld.shared.u32 %0, [%1];" : "=r"(v) : "r"(a)); return v;
}
__device__ __forceinline__ void sts_v4(uint32_t a, uint32_t x, uint32_t y, uint32_t z, uint32_t w) {
    asm volatile("st.shared.v4.u32 [%0], {%1,%2,%3,%4};" :: "r"(a), "r"(x), "r"(y), "r"(z), "r"(w) : "memory");
}
__device__ __forceinline__ void stg_cs(float4* p, float4 v) {
    asm volatile("st.global.cs.v4.f32 [%0], {%1,%2,%3,%4};"
                 :: "l"(p), "f"(v.x), "f"(v.y), "f"(v.z), "f"(v.w) : "memory");
}

// fp16 split of two adjacent fp32 values -> (hi half2, lo half2)
__device__ __forceinline__ void h2_split(float f0, float f1, uint32_t& hi, uint32_t& lo) {
    half2 h = __floats2half2_rn(f0, f1);
    float2 hf = __half22float2(h);
    half2 l = __floats2half2_rn(f0 - hf.x, f1 - hf.y);
    hi = *(uint32_t*)&h;
    lo = *(uint32_t*)&l;
}

__device__ __forceinline__ void mma_f16(float* d, const uint32_t* a, uint32_t b0, uint32_t b1) {
    asm volatile(
        "mma.sync.aligned.m16n8k16.row.col.f32.f16.f16.f32 "
        "{%0,%1,%2,%3}, {%4,%5,%6,%7}, {%8,%9}, {%0,%1,%2,%3};"
        : "+f"(d[0]), "+f"(d[1]), "+f"(d[2]), "+f"(d[3])
        : "r"(a[0]), "r"(a[1]), "r"(a[2]), "r"(a[3]), "r"(b0), "r"(b1));
}

// ---------------------------------------------------------------------------
// GEMM (R10 config — best measured): h = relu(x @ W1 + b1)
// ---------------------------------------------------------------------------
#define A_WORDS (128 * 36)
#define B_WORDS (16 * 264)
#define STAGE_WORDS (A_WORDS + B_WORDS)
#define GEMM_SMEM (2 * STAGE_WORDS * 4)

__global__ __launch_bounds__(256, 2)
void hmma_gemm(const float* __restrict__ A, const float* __restrict__ W,
               const float* __restrict__ bias, float* __restrict__ C,
               int K, int relu)
{
    extern __shared__ uint32_t sm[];
    const uint32_t sbase = smem_u32(sm);

    const int t   = threadIdx.x;
    const int wid = t >> 5;
    const int lid = t & 31;
    const int g   = lid >> 2;
    const int t4  = lid & 3;
    const int wm  = wid & 3;
    const int wn  = wid >> 2;

    const int m0 = blockIdx.y * 128;
    const int n0 = blockIdx.x * 128;

    const int aRow = t >> 1;
    const int aP8  = (t & 1) * 8;
    const float* Ag = A + (size_t)(m0 + aRow) * K + aP8 * 2;
    const int bP = t >> 4;
    const int bN = (t & 15) * 8;
    const float* Bg = W + (size_t)(2 * bP) * HH + n0 + bN;

    const uint32_t aSts = sbase + (uint32_t)(aRow * 36 + aP8) * 4u;
    const uint32_t bSts = sbase + (uint32_t)(A_WORDS + bP * 264 + bN) * 4u;

    float acc[2][8][4];
#pragma unroll
    for (int i = 0; i < 2; i++)
#pragma unroll
        for (int j = 0; j < 8; j++)
#pragma unroll
            for (int q = 0; q < 4; q++) acc[i][j][q] = 0.0f;

    const int NC = K / 32;

    float4 ra[4], rb0[2], rb1[2];
#pragma unroll
    for (int q = 0; q < 4; q++) ra[q] = *(const float4*)(Ag + 4 * q);
#pragma unroll
    for (int q = 0; q < 2; q++) {
        rb0[q] = *(const float4*)(Bg + 4 * q);
        rb1[q] = *(const float4*)(Bg + HH + 4 * q);
    }

    for (int c = 0; c < NC; c++) {
        const uint32_t soff = (uint32_t)((c & 1) * STAGE_WORDS) * 4u;

        {
            const float* af = (const float*)ra;
            uint32_t hi[8], lo[8];
#pragma unroll
            for (int j = 0; j < 8; j++)
                h2_split(af[2 * j], af[2 * j + 1], hi[j], lo[j]);
            sts_v4(aSts + soff,      hi[0], hi[1], hi[2], hi[3]);
            sts_v4(aSts + soff + 16, hi[4], hi[5], hi[6], hi[7]);
            sts_v4(aSts + soff + 64, lo[0], lo[1], lo[2], lo[3]);
            sts_v4(aSts + soff + 80, lo[4], lo[5], lo[6], lo[7]);

            const float* b0f = (const float*)rb0;
            const float* b1f = (const float*)rb1;
#pragma unroll
            for (int j = 0; j < 8; j++)
                h2_split(b0f[j], b1f[j], hi[j], lo[j]);
            sts_v4(bSts + soff,       hi[0], hi[1], hi[2], hi[3]);
            sts_v4(bSts + soff + 16,  hi[4], hi[5], hi[6], hi[7]);
            sts_v4(bSts + soff + 528, lo[0], lo[1], lo[2], lo[3]);
            sts_v4(bSts + soff + 544, lo[4], lo[5], lo[6], lo[7]);
        }
        __syncthreads();

        if (c + 1 < NC) {
            const float* ap = Ag + (size_t)(c + 1) * 32;
#pragma unroll
            for (int q = 0; q < 4; q++) ra[q] = *(const float4*)(ap + 4 * q);
            const float* bp = Bg + (size_t)(c + 1) * 32 * HH;
#pragma unroll
            for (int q = 0; q < 2; q++) {
                rb0[q] = *(const float4*)(bp + 4 * q);
                rb1[q] = *(const float4*)(bp + HH + 4 * q);
            }
        }

        const uint32_t sA = sbase + soff;
        const uint32_t sB = sbase + soff + A_WORDS * 4u;

#pragma unroll
        for (int ks = 0; ks < 2; ks++) {
            uint32_t Ahi[2][4], Alo[2][4];
#pragma unroll
            for (int mt = 0; mt < 2; mt++) {
                const uint32_t r0 = (uint32_t)(wm * 32 + mt * 16 + g) * 36u;
                const uint32_t r8 = r0 + 8u * 36u;
                const uint32_t p  = (uint32_t)(8 * ks + t4);
                Ahi[mt][0] = lds_u32(sA + (r0 + p) * 4u);
                Ahi[mt][1] = lds_u32(sA + (r8 + p) * 4u);
                Ahi[mt][2] = lds_u32(sA + (r0 + p + 4u) * 4u);
                Ahi[mt][3] = lds_u32(sA + (r8 + p + 4u) * 4u);
                Alo[mt][0] = lds_u32(sA + (r0 + p + 16u) * 4u);
                Alo[mt][1] = lds_u32(sA + (r8 + p + 16u) * 4u);
                Alo[mt][2] = lds_u32(sA + (r0 + p + 20u) * 4u);
                Alo[mt][3] = lds_u32(sA + (r8 + p + 20u) * 4u);
            }
            const uint32_t pr0 = (uint32_t)(8 * ks + t4) * 264u;
            const uint32_t pr1 = pr0 + 4u * 264u;
#pragma unroll
            for (int nt = 0; nt < 8; nt++) {
                const uint32_t n = (uint32_t)(wn * 64 + nt * 8 + g);
                uint32_t bh0 = lds_u32(sB + (pr0 + n) * 4u);
                uint32_t bh1 = lds_u32(sB + (pr1 + n) * 4u);
                uint32_t bl0 = lds_u32(sB + (pr0 + 132u + n) * 4u);
                uint32_t bl1 = lds_u32(sB + (pr1 + 132u + n) * 4u);
#pragma unroll
                for (int mt = 0; mt < 2; mt++) {
                    mma_f16(acc[mt][nt], Ahi[mt], bh0, bh1);
                    mma_f16(acc[mt][nt], Alo[mt], bh0, bh1);
                    mma_f16(acc[mt][nt], Ahi[mt], bl0, bl1);
                }
            }
        }
        __syncthreads();
    }

#pragma unroll
    for (int mt = 0; mt < 2; mt++) {
        int row = m0 + wm * 32 + mt * 16 + g;
#pragma unroll
        for (int nt = 0; nt < 8; nt++) {
            int col = n0 + wn * 64 + nt * 8 + 2 * t4;
            float2 bv = *(const float2*)(bias + col);
            float v0 = acc[mt][nt][0] + bv.x;
            float v1 = acc[mt][nt][1] + bv.y;
            float v2 = acc[mt][nt][2] + bv.x;
            float v3 = acc[mt][nt][3] + bv.y;
            if (relu) {
                v0 = fmaxf(v0, 0.f); v1 = fmaxf(v1, 0.f);
                v2 = fmaxf(v2, 0.f); v3 = fmaxf(v3, 0.f);
            }
            *(float2*)(C + (size_t)row * HH + col) = make_float2(v0, v1);
            *(float2*)(C + (size_t)(row + 8) * HH + col) = make_float2(v2, v3);
        }
    }
}

// ---------------------------------------------------------------------------
__global__ void reset_kernel() { g_fb_count = 0; }

// ---------------------------------------------------------------------------
// Wc = W2 @ Ws  [2048 x 48]
// ---------------------------------------------------------------------------
__global__ __launch_bounds__(256, 4)
void wc_kernel(const float* __restrict__ W2, const float* __restrict__ Ws)
{
    __shared__ float es[16][128];
    __shared__ float ws[128][48];

    int r0 = blockIdx.x * 16;
    int t  = threadIdx.x;
    int r  = t >> 4;
    int c  = t & 15;

    float a0 = 0.f, a1 = 0.f, a2 = 0.f;

    for (int k0 = 0; k0 < HH; k0 += 128) {
        for (int i = t; i < 512; i += 256) {
            int rr = i >> 5, cc = (i & 31) << 2;
            *(float4*)&es[rr][cc] =
                *(const float4*)(W2 + (size_t)(r0 + rr) * HH + k0 + cc);
        }
        for (int i = t; i < 1536; i += 256) {
            int rr = i / 12, cc = (i % 12) << 2;
            *(float4*)&ws[rr][cc] = *(const float4*)(Ws + (size_t)(k0 + rr) * 48 + cc);
        }
        __syncthreads();
        float p0 = 0.f, p1 = 0.f, p2 = 0.f;
#pragma unroll 4
        for (int k = 0; k < 128; k++) {
            float e = es[r][k];
            p0 = fmaf(e, ws[k][c],      p0);
            p1 = fmaf(e, ws[k][c + 16], p1);
            p2 = fmaf(e, ws[k][c + 32], p2);
        }
        a0 += p0; a1 += p1; a2 += p2;
        __syncthreads();
    }

    g_wc[(size_t)(r0 + r) * 48 + c]      = a0;
    g_wc[(size_t)(r0 + r) * 48 + c + 16] = a1;
    g_wc[(size_t)(r0 + r) * 48 + c + 32] = a2;
}

// bc = b2 @ Ws + bs : one block per output, 256-thread tree reduction
__global__ __launch_bounds__(256, 4)
void bc_kernel(const float* __restrict__ b2, const float* __restrict__ Ws,
               const float* __restrict__ bs)
{
    __shared__ float red[256];
    int j = blockIdx.x;
    int t = threadIdx.x;
    float a = 0.f;
    for (int k = t; k < HH; k += 256)
        a = fmaf(b2[k], Ws[(size_t)k * 48 + j], a);
    red[t] = a;
    __syncthreads();
    for (int s = 128; s > 0; s >>= 1) {
        if (t < s) red[t] += red[t + s];
        __syncthreads();
    }
    if (t == 0) g_bc[j] = red[0] + bs[j];
}

// ---------------------------------------------------------------------------
// logits = g_h @ g_wc + g_bc ; argmax -> g_idx ; near-ties flagged
// ---------------------------------------------------------------------------
__global__ __launch_bounds__(256, 4)
void logits_argmax_kernel(float* __restrict__ out_logits, int write_logits)
{
    __shared__ float es[16][128];
    __shared__ float ws[128][48];
    __shared__ float ls[16][48];
    __shared__ int   sflag[16];

    int b0 = blockIdx.x * 16;
    int t  = threadIdx.x;
    int r  = t >> 4;
    int c  = t & 15;

    if (t < 16) sflag[t] = 0;

    float acc0 = 0.f, acc1 = 0.f, acc2 = 0.f;

    for (int k0 = 0; k0 < HH; k0 += 128) {
        for (int i = t; i < 512; i += 256) {
            int rr = i >> 5, cc = (i & 31) << 2;
            *(float4*)&es[rr][cc] =
                *(const float4*)(g_h + (size_t)(b0 + rr) * HH + k0 + cc);
        }
        for (int i = t; i < 1536; i += 256) {
            int rr = i / 12, cc = (i % 12) << 2;
            *(float4*)&ws[rr][cc] = *(const float4*)(g_wc + (size_t)(k0 + rr) * 48 + cc);
        }
        __syncthreads();
        float p0 = 0.f, p1 = 0.f, p2 = 0.f;
#pragma unroll 4
        for (int k = 0; k < 128; k++) {
            float e = es[r][k];
            p0 = fmaf(e, ws[k][c],      p0);
            p1 = fmaf(e, ws[k][c + 16], p1);
            p2 = fmaf(e, ws[k][c + 32], p2);
        }
        acc0 += p0; acc1 += p1; acc2 += p2;
        __syncthreads();
    }

    ls[r][c]      = acc0 + g_bc[c];
    ls[r][c + 16] = acc1 + g_bc[c + 16];
    ls[r][c + 32] = acc2 + g_bc[c + 32];
    __syncthreads();

    if (write_logits) {
        for (int i = t; i < 16 * 48; i += 256) {
            int rr = i / 48, cc = i % 48;
            out_logits[(size_t)(b0 + rr) * 48 + cc] = ls[rr][cc];
        }
    }
    if (t < 128) {
        int rr = t >> 3, tt = t & 7;
        const float* lp = &ls[rr][tt * 6];
        float best = lp[0], second = -3.4e38f;
        int bi = 0;
#pragma unroll
        for (int m = 1; m < 6; m++) {
            float v = lp[m];
            if (v > best) { second = best; best = v; bi = m; }
            else if (v > second) second = v;
        }
        g_idx[(b0 + rr) * TT + tt] = bi;
        if (best - second < GAP_THR) sflag[rr] = 1;
    }
    __syncthreads();
    if (t < 16 && sflag[t]) {
        int pos = atomicAdd(&g_fb_count, 1);
        g_fb_list[pos] = b0 + t;
    }
}

// ---------------------------------------------------------------------------
// Exact fp32 fallback for flagged samples
// ---------------------------------------------------------------------------
__global__ __launch_bounds__(256, 1)
void fallback_kernel(const float* __restrict__ x,
                     const float* __restrict__ W1, const float* __restrict__ b1,
                     const float* __restrict__ W2, const float* __restrict__ b2,
                     const float* __restrict__ Ws, const float* __restrict__ bs)
{
    __shared__ float xs[1024];
    __shared__ float hs[2048];
    __shared__ float es2[2048];
    __shared__ float ls[48];

    const int t = threadIdx.x;
    const int total = g_fb_count;

    for (int idx = blockIdx.x; idx < total; idx += gridDim.x) {
        const int b = g_fb_list[idx];

        float ha[8];
#pragma unroll
        for (int m = 0; m < 8; m++) ha[m] = 0.f;
        for (int k0 = 0; k0 < DD; k0 += 1024) {
            __syncthreads();
            for (int i = t; i < 256; i += 256)
                *(float4*)&xs[i * 4] = *(const float4*)(x + (size_t)b * DD + k0 + i * 4);
            __syncthreads();
            for (int k = 0; k < 1024; k++) {
                float xv = xs[k];
                const float* wrow = W1 + (size_t)(k0 + k) * HH + t;
#pragma unroll
                for (int m = 0; m < 8; m++)
                    ha[m] = fmaf(xv, wrow[256 * m], ha[m]);
            }
        }
        __syncthreads();
#pragma unroll
        for (int m = 0; m < 8; m++)
            hs[t + 256 * m] = fmaxf(ha[m] + b1[t + 256 * m], 0.f);
        __syncthreads();

        float ea[8];
#pragma unroll
        for (int m = 0; m < 8; m++) ea[m] = 0.f;
        for (int k = 0; k < HH; k++) {
            float hv = hs[k];
            const float* wrow = W2 + (size_t)k * HH + t;
#pragma unroll
            for (int m = 0; m < 8; m++)
                ea[m] = fmaf(hv, wrow[256 * m], ea[m]);
        }
#pragma unroll
        for (int m = 0; m < 8; m++)
            es2[t + 256 * m] = ea[m] + b2[t + 256 * m];
        __syncthreads();

        if (t < 48) {
            float a = 0.f;
            for (int k = 0; k < HH; k++)
                a = fmaf(es2[k], Ws[(size_t)k * 48 + t], a);
            ls[t] = a + bs[t];
        }
        __syncthreads();
        if (t < 8) {
            const float* lp = &ls[t * 6];
            float best = lp[0]; int bi = 0;
#pragma unroll
            for (int m = 1; m < 6; m++) {
                float v = lp[m];
                if (v > best) { best = v; bi = m; }
            }
            g_idx[b * TT + t] = bi;
        }
        __syncthreads();
    }
}

// ---------------------------------------------------------------------------
// Bitonic sort of rows [b_off, b_off+grid) of x -> g_xs
// ---------------------------------------------------------------------------
__global__ __launch_bounds__(1024, 2)
void sort_rows_kernel(const float* __restrict__ x, int b_off)
{
    __shared__ float s[4096];
    int b = blockIdx.x + b_off;
    const float* xp = x + (size_t)b * DD;
    for (int i = threadIdx.x; i < 4096; i += 1024) s[i] = xp[i];
    __syncthreads();

    for (int k = 2; k <= 4096; k <<= 1) {
        for (int j = k >> 1; j > 0; j >>= 1) {
#pragma unroll
            for (int base = 0; base < 4096; base += 1024) {
                int i   = base + threadIdx.x;
                int ixj = i ^ j;
                if (ixj > i) {
                    bool asc = ((i & k) == 0);
                    float a = s[i], bb = s[ixj];
                    if ((a > bb) == asc) { s[i] = bb; s[ixj] = a; }
                }
            }
            __syncthreads();
        }
    }
    float* op = g_xs + (size_t)b * DD;
    for (int i = threadIdx.x; i < 4096; i += 1024) op[i] = s[i];
}

// ---------------------------------------------------------------------------
// Collapsed scan + emit: outputs[b,t,:] = a_t * perm_t(x_b) + c_t
// ---------------------------------------------------------------------------
__global__ __launch_bounds__(512, 4)
void emit_kernel(const float* __restrict__ x,
                 const float* __restrict__ add_s, const float* __restrict__ sub_s,
                 const float* __restrict__ mul_s, const float* __restrict__ div_s,
                 float* __restrict__ out)
{
    __shared__ float sa[8], sb[8];
    __shared__ int   sm8[8];
    int b = blockIdx.x;

    if (threadIdx.x == 0) {
        float A = 1.0f, Bc = 0.0f;
        int mode = 0;
        float ad = *add_s, su = *sub_s, mu = *mul_s;
        float dv = *div_s + 1e-5f;
#pragma unroll
        for (int t = 0; t < 8; t++) {
            int m = g_idx[b * 8 + t];
            switch (m) {
                case 0: mode = 2;              break;
                case 1: mode ^= 1;             break;
                case 2: Bc += ad;              break;
                case 3: Bc -= su;              break;
                case 4: A *= mu; Bc *= mu;     break;
                case 5: A /= dv; Bc /= dv;     break;
            }
            sa[t] = A; sb[t] = Bc; sm8[t] = mode;
        }
    }
    __syncthreads();

    const float4* xr  = (const float4*)(x    + (size_t)b * DD);
    const float4* xsr = (const float4*)(g_xs + (size_t)b * DD);
    float* ob = out + (size_t)b * ((size_t)TT * DD);
    const int Q = DD / 4;

#pragma unroll 1
    for (int t = 0; t < 8; t++) {
        float A = sa[t], Bc = sb[t];
        int mode = sm8[t];
        const float4* src = (mode & 2) ? xsr : xr;
        bool rev = (mode & 1);
        float4* op = (float4*)(ob + (size_t)t * DD);
#pragma unroll
        for (int u = 0; u < 2; u++) {
            int i = threadIdx.x + 512 * u;
            float4 v;
            if (!rev) {
                v = src[i];
            } else {
                float4 w = src[Q - 1 - i];
                v.x = w.w; v.y = w.z; v.z = w.y; v.w = w.x;
            }
            v.x = fmaf(A, v.x, Bc);
            v.y = fmaf(A, v.y, Bc);
            v.z = fmaf(A, v.z, Bc);
            v.w = fmaf(A, v.w, Bc);
            stg_cs(&op[i], v);
        }
    }
}

// ---------------------------------------------------------------------------
extern "C" void kernel_launch(void* const* d_in, const int* in_sizes, int n_in,
                              void* d_out, int out_size)
{
    const float* x     = (const float*)d_in[0];
    const float* W1    = (const float*)d_in[1];
    const float* b1    = (const float*)d_in[2];
    const float* W2    = (const float*)d_in[3];
    const float* b2    = (const float*)d_in[4];
    const float* Ws    = (const float*)d_in[5];
    const float* bs    = (const float*)d_in[6];
    const float* add_s = (const float*)d_in[7];
    const float* sub_s = (const float*)d_in[8];
    const float* mul_s = (const float*)d_in[9];
    const float* div_s = (const float*)d_in[10];
    float* out = (float*)d_out;

    const size_t out_main = (size_t)BB * TT * DD;
    const size_t out_need = out_main + (size_t)BB * TT * MM;
    int write_logits = ((size_t)out_size >= out_need) ? 1 : 0;
    float* out_logits = out + out_main;

    // one-time host-side objects (identical DAG every call)
    static cudaStream_t s_aux = nullptr;
    static cudaEvent_t ev_fork = nullptr, ev_join = nullptr;
    if (s_aux == nullptr) {
        cudaStreamCreateWithFlags(&s_aux, cudaStreamNonBlocking);
        cudaEventCreateWithFlags(&ev_fork, cudaEventDisableTiming);
        cudaEventCreateWithFlags(&ev_join, cudaEventDisableTiming);
        cudaFuncSetAttribute(hmma_gemm, cudaFuncAttributeMaxDynamicSharedMemorySize, GEMM_SMEM);
    }

    float* d_gh;  cudaGetSymbolAddress((void**)&d_gh,  g_h);

    // serial head on main stream
    reset_kernel<<<1, 1>>>();

    // fork: aux stream runs sort + wc + bc concurrently with gemm1
    cudaEventRecord(ev_fork, 0);
    cudaStreamWaitEvent(s_aux, ev_fork, 0);

    sort_rows_kernel<<<BB / 2, 1024, 0, s_aux>>>(x, 0);
    sort_rows_kernel<<<BB / 2, 1024, 0, s_aux>>>(x, BB / 2);

    dim3 g(HH / 128, BB / 128);
    hmma_gemm<<<g, 256, GEMM_SMEM>>>(x, W1, b1, d_gh, DD, 1);   // main stream (profiled slot 3)

    wc_kernel<<<HH / 16, 256, 0, s_aux>>>(W2, Ws);
    bc_kernel<<<48, 256, 0, s_aux>>>(b2, Ws, bs);

    // join
    cudaEventRecord(ev_join, s_aux);
    cudaStreamWaitEvent(0, ev_join, 0);

    logits_argmax_kernel<<<BB / 16, 256>>>(out_logits, write_logits);

    fallback_kernel<<<128, 256>>>(x, W1, b1, W2, b2, Ws, bs);

    emit_kernel<<<BB, 512>>>(x, add_s, sub_s, mul_s, div_s, out);
}